// round 12
// baseline (speedup 1.0000x reference)
#include <cuda_runtime.h>
#include <cstdint>

#define BATCH 64
#define SEQ   512
#define IDIM  300
#define HID   600
#define GATES 2400
#define NBLK  75          // column-blocks per direction (150 total; GB300 has 152 SMs)
#define NH    8           // hidden units per block
#define NW    32          // gate columns per block (4 gates x 8)
#define NTHR  256
#define KTOT  900
#define KC    100         // k per chunk
#define KCH   50          // k per warpgroup per chunk
#define NCH   9           // 3 x-chunks then 6 h-chunks
#define NSTG  3           // smem ring stages
#define CHFL  (KC*BATCH)          // 6400 floats
#define CHBYTES (CHFL*4)          // 25600 B
#define HSLAB (HID*BATCH)         // 38400 floats
#define XSLAB (IDIM*BATCH)        // 19200 floats

// ---------------- device scratch (static; no allocation) ----------------
__device__ __align__(16) float g_xt[2ull*SEQ*XSLAB];   // [dir][t][d*64+b]
__device__ __align__(16) float g_h[2*2*HSLAB];         // [dir][parity][k*64+b]
__device__ int g_bar[2*SEQ];

// ---------------- helpers ----------------
__device__ __forceinline__ float2 ffma2(float2 a, float2 b, float2 c) {
    float2 d;
    asm("fma.rn.f32x2 %0, %1, %2, %3;"
        : "=l"(*(unsigned long long*)&d)
        : "l"(*(unsigned long long*)&a),
          "l"(*(unsigned long long*)&b),
          "l"(*(unsigned long long*)&c));
    return d;
}
__device__ __forceinline__ void mbar_init(uint32_t a, uint32_t cnt) {
    asm volatile("mbarrier.init.shared.b64 [%0], %1;" :: "r"(a), "r"(cnt) : "memory");
}
__device__ __forceinline__ void mbar_expect(uint32_t a, uint32_t bytes) {
    asm volatile("mbarrier.arrive.expect_tx.shared.b64 _, [%0], %1;"
                 :: "r"(a), "r"(bytes) : "memory");
}
__device__ __forceinline__ void bulk_g2s(uint32_t dst, const float* src, uint32_t bytes, uint32_t mbar) {
    asm volatile("cp.async.bulk.shared::cluster.global.mbarrier::complete_tx::bytes "
                 "[%0], [%1], %2, [%3];"
                 :: "r"(dst), "l"(src), "r"(bytes), "r"(mbar) : "memory");
}
__device__ __forceinline__ void mbar_wait(uint32_t a, int ph) {
    asm volatile(
        "{\n\t.reg .pred P;\n\t"
        "WL%=:\n\t"
        "mbarrier.try_wait.parity.acquire.cta.shared::cta.b64 P, [%0], %1, 0x989680;\n\t"
        "@P bra WD%=;\n\t"
        "bra WL%=;\n\t"
        "WD%=:\n\t}"
        :: "r"(a), "r"(ph) : "memory");
}
__device__ __forceinline__ float sigm(float x) { return 1.0f / (1.0f + __expf(-x)); }
__device__ __forceinline__ float tanh_s(float x) {
    float t = 1.0f - 2.0f / (__expf(2.0f * fabsf(x)) + 1.0f);
    return copysignf(t, x);
}

// ---------------- kernel: reset persistent state (per call) ----------------
__global__ void brnn_reset() {
    int i = blockIdx.x * blockDim.x + threadIdx.x;
    int st = gridDim.x * blockDim.x;
    for (int k = i; k < 2*2*HSLAB; k += st) g_h[k] = 0.0f;
    for (int k = i; k < 2*SEQ;     k += st) g_bar[k] = 0;
}

// ---------------- kernel: transpose x (+ backward-direction gather) ----------------
// g_xt[dir][t][d*64+b] = x[b][ts][d], ts = (dir && t<L_b) ? L_b-1-t : t
__global__ void brnn_xpose(const float* __restrict__ x, const int* __restrict__ len) {
    extern __shared__ float tile[];           // 64 * 301 floats
    __shared__ int L[BATCH];
    const int t = blockIdx.x, dir = blockIdx.y, tid = threadIdx.x;
    if (tid < BATCH) L[tid] = len[tid];
    __syncthreads();
    for (int idx = tid; idx < BATCH*IDIM; idx += NTHR) {
        int b = idx / IDIM, d = idx - b*IDIM;
        int ts = t;
        if (dir) { int l = L[b]; if (t < l) ts = l - 1 - t; }
        tile[b*301 + d] = x[((size_t)b*SEQ + ts)*IDIM + d];
    }
    __syncthreads();
    float* dst = g_xt + ((size_t)dir*SEQ + t)*XSLAB;
    for (int o = tid; o < XSLAB; o += NTHR)
        dst[o] = tile[(o & 63)*301 + (o >> 6)];
}

// ---------------- kernel: persistent bidirectional LSTM ----------------
__global__ void __launch_bounds__(NTHR, 1)
brnn_lstm(const float* __restrict__ Wf, const float* __restrict__ Uf, const float* __restrict__ bf,
          const float* __restrict__ Wb, const float* __restrict__ Ub, const float* __restrict__ bb,
          const int* __restrict__ lengths, float* __restrict__ out)
{
    const int dir = blockIdx.y, blk = blockIdx.x, tid = threadIdx.x;
    const int c0 = blk * NH;

    extern __shared__ __align__(16) float sm[];
    // [0..16): mbarrier area (3 x u64, 8B aligned)
    float* Ws  = sm + 16;                 // 900*32 = 28800
    float* As  = Ws  + KTOT*NW;           // 3*6400 = 19200 (16B-aligned offset)
    float* Zs  = As  + NSTG*CHFL;         // 64*33  = 2112  (wg0 partial + bias)
    float* Zs2 = Zs  + 64*33;             // 64*33  = 2112  (wg1 partial)
    float* Cs  = Zs2 + 64*33;             // 512
    float* Acc = Cs  + 512;               // 512
    float* bsm = Acc + 512;               // 32
    int*   lsm = (int*)(bsm + 32);        // 64

    const uint32_t smem_base = (uint32_t)__cvta_generic_to_shared(sm);
    const uint32_t mb0 = smem_base;                                  // stage mbarriers
    const uint32_t as0 = smem_base + (16 + KTOT*NW) * 4;             // As stage-0 smem addr

    const float* W  = dir ? Wb : Wf;
    const float* U  = dir ? Ub : Uf;
    const float* bd = dir ? bb : bf;

    // one-time setup: weight slice, bias, lengths, state, mbarriers
    for (int idx = tid; idx < KTOT*NW; idx += NTHR) {
        int r = idx >> 5, cc = idx & 31;
        int gc = (cc >> 3)*HID + c0 + (cc & 7);
        Ws[idx] = (r < IDIM) ? W[(size_t)r*GATES + gc]
                             : U[(size_t)(r - IDIM)*GATES + gc];
    }
    if (tid < NW) bsm[tid] = bd[(tid >> 3)*HID + c0 + (tid & 7)];
    if (tid < BATCH) lsm[tid] = lengths[tid];
    for (int idx = tid; idx < 512; idx += NTHR) { Cs[idx] = 0.0f; Acc[idx] = 0.0f; }
    if (tid == 0) { mbar_init(mb0, 1); mbar_init(mb0 + 8, 1); mbar_init(mb0 + 16, 1); }
    __syncthreads();

    // thread mapping: 2 warpgroups split k; tile = 8 rows x 2 cols
    const int wg   = tid >> 7;            // 0/1
    const int wtid = tid & 127;
    const int rowb = (wtid >> 4) * 8;     // 0,8,...,56
    const int col0 = (wtid & 15) * 2;     // 0,2,...,30

    float* gh = g_h + dir*2*HSLAB;
    const float* gx = g_xt + (size_t)dir*SEQ*XSLAB;
    int* bar = g_bar + dir*SEQ;

    int ph0 = 0, ph1 = 0, ph2 = 0;

    for (int s = 0; s < SEQ; s++) {
        const float* hr = gh + (s & 1)*HSLAB;
        float*       hw = gh + ((s + 1) & 1)*HSLAB;
        const float* xr = gx + (size_t)s*XSLAB;

        // prologue: issue x-chunks 0,1 (independent of previous step)
        if (tid == 0) {
            mbar_expect(mb0, CHBYTES);     bulk_g2s(as0,              xr,        CHBYTES, mb0);
            mbar_expect(mb0 + 8, CHBYTES); bulk_g2s(as0 + CHBYTES,    xr + CHFL, CHBYTES, mb0 + 8);
        }

        float2 a00 = {0.f,0.f}, a01 = {0.f,0.f}, a02 = {0.f,0.f}, a03 = {0.f,0.f};
        float2 a10 = {0.f,0.f}, a11 = {0.f,0.f}, a12 = {0.f,0.f}, a13 = {0.f,0.f};

        for (int c = 0; c < NCH; c++) {
            // h-chunks (c>=3) need step s-1 complete across all blocks of this dir
            if (c == 1 && s > 0) {
                if (tid == 0)
                    while (*(volatile int*)&bar[s-1] < NBLK) __nanosleep(40);
                __syncthreads();
            }
            if (tid == 0 && c + 2 < NCH) {
                const int nc = c + 2;
                const int stg = nc % NSTG;
                const float* src = (nc < 3) ? xr + nc*CHFL : hr + (nc - 3)*CHFL;
                mbar_expect(mb0 + stg*8, CHBYTES);
                bulk_g2s(as0 + stg*CHBYTES, src, CHBYTES, mb0 + stg*8);
            }

            // wait for chunk c's data
            const int stg = c % NSTG;
            int ph = (stg == 0) ? ph0 : (stg == 1) ? ph1 : ph2;
            mbar_wait(mb0 + stg*8, ph);
            if (stg == 0) ph0 ^= 1; else if (stg == 1) ph1 ^= 1; else ph2 ^= 1;

            const float* Ap = As + stg*CHFL + wg*KCH*BATCH + rowb;
            const float* Wp = Ws + (c*KC + wg*KCH)*NW + col0;
            #pragma unroll 10
            for (int k = 0; k < KCH; k++) {
                const float4 v0 = *(const float4*)(Ap + k*BATCH);
                const float4 v1 = *(const float4*)(Ap + k*BATCH + 4);
                const float2 w  = *(const float2*)(Wp + k*NW);
                const float2 w0 = make_float2(w.x, w.x);
                const float2 w1 = make_float2(w.y, w.y);
                a00 = ffma2(make_float2(v0.x, v0.y), w0, a00);
                a01 = ffma2(make_float2(v0.z, v0.w), w0, a01);
                a02 = ffma2(make_float2(v1.x, v1.y), w0, a02);
                a03 = ffma2(make_float2(v1.z, v1.w), w0, a03);
                a10 = ffma2(make_float2(v0.x, v0.y), w1, a10);
                a11 = ffma2(make_float2(v0.z, v0.w), w1, a11);
                a12 = ffma2(make_float2(v1.x, v1.y), w1, a12);
                a13 = ffma2(make_float2(v1.z, v1.w), w1, a13);
            }
            __syncthreads();   // chunk-c buffer free before producer re-arms it
        }

        // stage partials: wg0 -> Zs (+bias), wg1 -> Zs2 (raw)
        {
            float* Zt = wg ? Zs2 : Zs;
            const float ad0 = wg ? 0.f : bsm[col0];
            const float ad1 = wg ? 0.f : bsm[col0 + 1];
            Zt[(rowb+0)*33 + col0] = a00.x + ad0;  Zt[(rowb+1)*33 + col0] = a00.y + ad0;
            Zt[(rowb+2)*33 + col0] = a01.x + ad0;  Zt[(rowb+3)*33 + col0] = a01.y + ad0;
            Zt[(rowb+4)*33 + col0] = a02.x + ad0;  Zt[(rowb+5)*33 + col0] = a02.y + ad0;
            Zt[(rowb+6)*33 + col0] = a03.x + ad0;  Zt[(rowb+7)*33 + col0] = a03.y + ad0;
            Zt[(rowb+0)*33 + col0+1] = a10.x + ad1;  Zt[(rowb+1)*33 + col0+1] = a10.y + ad1;
            Zt[(rowb+2)*33 + col0+1] = a11.x + ad1;  Zt[(rowb+3)*33 + col0+1] = a11.y + ad1;
            Zt[(rowb+4)*33 + col0+1] = a12.x + ad1;  Zt[(rowb+5)*33 + col0+1] = a12.y + ad1;
            Zt[(rowb+6)*33 + col0+1] = a13.x + ad1;  Zt[(rowb+7)*33 + col0+1] = a13.y + ad1;
        }
        __syncthreads();

        // gates: 512 cells (j,b), 2 per thread; cell = j*64+b
        #pragma unroll
        for (int u = 0; u < 2; u++) {
            int cell = tid + u*NTHR;
            int j = cell >> 6, b = cell & 63;
            float zi = Zs[b*33 + j]      + Zs2[b*33 + j];
            float zf = Zs[b*33 + 8 + j]  + Zs2[b*33 + 8 + j];
            float zg = Zs[b*33 + 16 + j] + Zs2[b*33 + 16 + j];
            float zo = Zs[b*33 + 24 + j] + Zs2[b*33 + 24 + j];
            float ig = sigm(zi), fg = sigm(zf), gg = tanh_s(zg), og = sigm(zo);
            float cn = fg * Cs[cell] + ig * gg;
            Cs[cell] = cn;
            float h = og * tanh_s(cn);
            hw[(c0 + j)*BATCH + b] = h;
            if (s < lsm[b]) Acc[cell] += h;
        }
        __threadfence();                 // make h STGs globally visible (all writers)
        __syncthreads();
        if (tid == 0) atomicAdd(&bar[s], 1);   // release step s
    }

    const float inv = 1.0f / (float)SEQ;
    for (int idx = tid; idx < 512; idx += NTHR) {
        int j = idx >> 6, b = idx & 63;
        out[b*1200 + dir*HID + c0 + j] = Acc[idx] * inv;
    }
}

// ---------------- launch ----------------
extern "C" void kernel_launch(void* const* d_in, const int* in_sizes, int n_in,
                              void* d_out, int out_size) {
    (void)in_sizes; (void)out_size;
    const float* x   = (const float*)d_in[0];
    const int*   len = (const int*)d_in[1];
    int base = (n_in >= 9) ? 3 : 2;           // skip scalar 'training' if present
    const float* Wf = (const float*)d_in[base + 0];
    const float* Uf = (const float*)d_in[base + 1];
    const float* bf = (const float*)d_in[base + 2];
    const float* Wb = (const float*)d_in[base + 3];
    const float* Ub = (const float*)d_in[base + 4];
    const float* bb = (const float*)d_in[base + 5];
    float* out = (float*)d_out;

    const int xpose_smem = 64 * 301 * (int)sizeof(float);                 // 77056 B
    const int lstm_smem  = (16 + KTOT*NW + NSTG*CHFL + 2*64*33 + 512 + 512 + 32) * (int)sizeof(float)
                         + 64 * (int)sizeof(int);                          // 213440 B
    cudaFuncSetAttribute(brnn_xpose, cudaFuncAttributeMaxDynamicSharedMemorySize, xpose_smem);
    cudaFuncSetAttribute(brnn_lstm,  cudaFuncAttributeMaxDynamicSharedMemorySize, lstm_smem);

    brnn_reset<<<128, 256>>>();
    brnn_xpose<<<dim3(SEQ, 2), NTHR, xpose_smem>>>(x, len);
    brnn_lstm<<<dim3(NBLK, 2), NTHR, lstm_smem>>>(Wf, Uf, bf, Wb, Ub, bb, len, out);
}

// round 16
// speedup vs baseline: 2.2814x; 2.2814x over previous
#include <cuda_runtime.h>
#include <cuda_bf16.h>
#include <cstdint>

#define BATCH 64
#define SEQ   512
#define IDIM  300
#define HID   600
#define GATES 2400
#define NBLK  75
#define NTHR  256
#define NCH   15             // K chunks of 64: 5 x-chunks (x300+bias+pad->320), 10 h-chunks (600+pad->640)
// smem layout (bytes)
#define SM_W   1024                    // weight frags: per chunk 8KB (hi 4KB, lo 4KB)
#define SM_STG (SM_W + NCH*8192)       // 123904: 3 stages x 16KB A tiles (hi 8KB, lo 8KB)
#define SM_Z   (SM_STG + 3*16384)      // 173056: Zs 8448B + Zs2 8448B
#define SM_TOT (SM_Z + 2*8448)         // 189952

// ---------------- device scratch (static; no allocation) ----------------
__device__ uint32_t g_xA[(size_t)2*SEQ*5*4096];  // x tiles in A-fragment layout
__device__ uint32_t g_hA[2*2*10*4096];           // h tiles [dir][parity][chunk]
__device__ int g_bar[2*SEQ];

// ---------------- asm helpers ----------------
__device__ __forceinline__ void mbar_init(uint32_t a, uint32_t c) {
    asm volatile("mbarrier.init.shared.b64 [%0], %1;" :: "r"(a), "r"(c) : "memory");
}
__device__ __forceinline__ void mbar_expect(uint32_t a, uint32_t bytes) {
    asm volatile("mbarrier.arrive.expect_tx.shared.b64 _, [%0], %1;" :: "r"(a), "r"(bytes) : "memory");
}
__device__ __forceinline__ void bulk_g2s(uint32_t dst, const void* src, uint32_t bytes, uint32_t mb) {
    asm volatile("cp.async.bulk.shared::cluster.global.mbarrier::complete_tx::bytes [%0], [%1], %2, [%3];"
                 :: "r"(dst), "l"(src), "r"(bytes), "r"(mb) : "memory");
}
__device__ __forceinline__ void mbar_wait(uint32_t a, int ph) {
    asm volatile("{\n\t.reg .pred P;\n\tWL%=:\n\t"
        "mbarrier.try_wait.parity.acquire.cta.shared::cta.b64 P, [%0], %1, 0x989680;\n\t"
        "@P bra WD%=;\n\tbra WL%=;\n\tWD%=:\n\t}" :: "r"(a), "r"(ph) : "memory");
}
__device__ __forceinline__ void mma16816(float* d, const uint32_t* a, uint32_t b0, uint32_t b1) {
    asm volatile("mma.sync.aligned.m16n8k16.row.col.f32.bf16.bf16.f32 "
        "{%0,%1,%2,%3}, {%4,%5,%6,%7}, {%8,%9}, {%0,%1,%2,%3};"
        : "+f"(d[0]), "+f"(d[1]), "+f"(d[2]), "+f"(d[3])
        : "r"(a[0]), "r"(a[1]), "r"(a[2]), "r"(a[3]), "r"(b0), "r"(b1));
}
__device__ __forceinline__ float sigm(float x) { return 1.0f / (1.0f + __expf(-x)); }
__device__ __forceinline__ float tanh_s(float x) {
    float t = 1.0f - 2.0f / (__expf(2.0f * fabsf(x)) + 1.0f);
    return copysignf(t, x);
}
__device__ __forceinline__ uint32_t bf2_hi(float a, float b, float& ra, float& rb) {
    __nv_bfloat162 v; v.x = __float2bfloat16_rn(a); v.y = __float2bfloat16_rn(b);
    ra = a - __bfloat162float(v.x); rb = b - __bfloat162float(v.y);
    return *(uint32_t*)&v;
}
__device__ __forceinline__ uint32_t bf2(float a, float b) {
    __nv_bfloat162 v; v.x = __float2bfloat16_rn(a); v.y = __float2bfloat16_rn(b);
    return *(uint32_t*)&v;
}

// ---------------- reset ----------------
__global__ void brnn_reset() {
    int i = blockIdx.x*blockDim.x + threadIdx.x, st = gridDim.x*blockDim.x;
    for (int k = i; k < 2*2*10*4096; k += st) g_hA[k] = 0u;
    for (int k = i; k < 2*SEQ; k += st) g_bar[k] = 0;
}

// ---------------- x -> A-fragment-layout bf16 hi/lo tiles (backward gather, bias row) ----------------
__global__ void brnn_xprep(const float* __restrict__ x, const int* __restrict__ len) {
    const int t = blockIdx.x, dir = blockIdx.y, tid = threadIdx.x;
    __shared__ int L[BATCH];
    if (tid < BATCH) L[tid] = len[tid];
    __syncthreads();
    uint32_t* base = g_xA + ((size_t)(dir*SEQ + t)*5) * 4096;
    for (int slot = tid; slot < 5*2048; slot += NTHR) {
        int ch = slot >> 11, off = slot & 2047;
        int a = off & 3, lane = (off >> 2) & 31, mtg = off >> 7;
        int mt = mtg & 3, g = mtg >> 2;
        int lm = (a & 1)*8 + (lane >> 2);
        int m  = mt*16 + lm;
        int lk = ((a >> 1))*8 + (lane & 3)*2;
        int k  = ch*64 + g*16 + lk;
        int ts = t;
        if (dir) { int l = L[m]; if (t < l) ts = l - 1 - t; }
        const float* xs = x + ((size_t)m*SEQ + ts)*IDIM;
        float v0 = (k   < IDIM) ? xs[k]   : (k   == IDIM ? 1.0f : 0.0f);
        float v1 = (k+1 < IDIM) ? xs[k+1] : (k+1 == IDIM ? 1.0f : 0.0f);
        float r0, r1;
        uint32_t hi = bf2_hi(v0, v1, r0, r1);
        uint32_t lo = bf2(r0, r1);
        uint32_t* tb = base + (size_t)ch*4096;
        tb[off] = hi; tb[2048 + off] = lo;
    }
}

// ---------------- persistent bidirectional LSTM (bf16-split mma.sync) ----------------
__global__ void __launch_bounds__(NTHR, 1)
brnn_lstm(const float* __restrict__ Wf, const float* __restrict__ Uf, const float* __restrict__ bf,
          const float* __restrict__ Wb, const float* __restrict__ Ub, const float* __restrict__ bb,
          const int* __restrict__ lengths, float* __restrict__ out)
{
    const int dir = blockIdx.y, blk = blockIdx.x, tid = threadIdx.x;
    const int wid = tid >> 5, lane = tid & 31;
    const int mt = wid & 3, gh = wid >> 2;
    const int c0 = blk * 8;

    extern __shared__ __align__(1024) char sm[];
    const uint32_t smb = (uint32_t)__cvta_generic_to_shared(sm);
    const uint32_t bm = smb;                    // 3 stage mbarriers @ 0,8,16
    float* Zs  = (float*)(sm + SM_Z);
    float* Zs2 = Zs + 2112;

    const float* W  = dir ? Wb : Wf;
    const float* U  = dir ? Ub : Uf;
    const float* bd = dir ? bb : bf;

    // ---- one-time: weights -> B-fragment layout bf16 hi/lo in smem ----
    for (int idx = tid; idx < NCH*1024; idx += NTHR) {
        int c = idx >> 10, rem = idx & 1023;
        int g = rem >> 8, rem2 = rem & 255;
        int ls = rem2 >> 3, r = rem2 & 7;
        int nt = r >> 1, kk = r & 1;
        int k0 = c*64 + g*16 + kk*8 + (ls & 3)*2;
        int n  = nt*8 + (ls >> 2);
        int gc = (n >> 3)*HID + c0 + (n & 7);
        float v0 = 0.f, v1 = 0.f;
        int k1 = k0 + 1;
        if (k0 < IDIM) v0 = W[(size_t)k0*GATES + gc];
        else if (k0 == IDIM) v0 = bd[gc];
        else if (k0 >= 320 && k0 < 920) v0 = U[(size_t)(k0-320)*GATES + gc];
        if (k1 < IDIM) v1 = W[(size_t)k1*GATES + gc];
        else if (k1 == IDIM) v1 = bd[gc];
        else if (k1 >= 320 && k1 < 920) v1 = U[(size_t)(k1-320)*GATES + gc];
        float r0, r1;
        uint32_t hi = bf2_hi(v0, v1, r0, r1);
        uint32_t lo = bf2(r0, r1);
        uint32_t boff = ((g*32 + ls)*8 + r)*4;
        *(uint32_t*)(sm + SM_W + c*8192 + boff)        = hi;
        *(uint32_t*)(sm + SM_W + c*8192 + 4096 + boff) = lo;
    }
    if (tid == 0) { mbar_init(bm, 1); mbar_init(bm+8, 1); mbar_init(bm+16, 1); }
    __syncthreads();

    // gate-thread state: warp wid handles hidden j=wid for b=lane and b=lane+32
    const int bA = lane, bB = lane + 32;
    float crA = 0.f, crB = 0.f, acA = 0.f, acB = 0.f;
    const int LA = lengths[bA], LB = lengths[bB];
    // h-store fragment offsets (constant): element (m=b, k=320+8*blk+wid)
    const int ch_h = blk >> 3;
    const int gl   = (8*(blk & 7) + wid) >> 4;
    auto hoff = [&](int b) -> int {
        int lm = b & 15, mtb = b >> 4;
        int au = (lm >> 3) + 2*(blk & 1);
        int lp = (lm & 7)*4 + (wid >> 1);
        return ((gl*4 + mtb)*32 + lp)*4 + au;
    };
    const int offA = hoff(bA), offB = hoff(bB);
    const int hsel = wid & 1;

    int* bar = g_bar + dir*SEQ;
    int ph0 = 0, ph1 = 0, ph2 = 0;

    for (int s = 0; s < SEQ; s++) {
        float acc[16];
        #pragma unroll
        for (int i = 0; i < 16; i++) acc[i] = 0.f;

        const uint32_t* xbase = g_xA + ((size_t)(dir*SEQ + s)*5)*4096;
        const uint32_t* hbase = g_hA + ((size_t)(dir*2 + (s & 1))*10)*4096;

        if (tid == 0) {
            mbar_expect(bm,     16384u); bulk_g2s(smb + SM_STG,         xbase,        16384u, bm);
            mbar_expect(bm + 8, 16384u); bulk_g2s(smb + SM_STG + 16384, xbase + 4096, 16384u, bm + 8);
        }

        for (int c = 0; c < NCH; c++) {
            if (tid == 0) {
                if (c == 3 && s > 0) {
                    while (*(volatile int*)&bar[s-1] < NBLK) __nanosleep(32);
                    __threadfence();
                    asm volatile("fence.proxy.async;" ::: "memory");
                }
                if (c + 2 < NCH) {
                    int nc = c + 2, st = nc % 3;
                    const uint32_t* src = (nc < 5) ? xbase + (size_t)nc*4096
                                                   : hbase + (size_t)(nc - 5)*4096;
                    mbar_expect(bm + st*8, 16384u);
                    bulk_g2s(smb + SM_STG + st*16384, src, 16384u, bm + st*8);
                }
            }
            const int st = c % 3;
            int ph = (st == 0) ? ph0 : (st == 1) ? ph1 : ph2;
            mbar_wait(bm + st*8, ph);
            if (st == 0) ph0 ^= 1; else if (st == 1) ph1 ^= 1; else ph2 ^= 1;

            const char* Ab = sm + SM_STG + st*16384;
            const char* Wc = sm + SM_W + c*8192;
            #pragma unroll
            for (int gi = 0; gi < 2; gi++) {
                const int g = gh*2 + gi;
                const uint4 ah = *(const uint4*)(Ab + ((g*4 + mt)*32 + lane)*16);
                const uint4 al = *(const uint4*)(Ab + 8192 + ((g*4 + mt)*32 + lane)*16);
                const uint4 bh0 = *(const uint4*)(Wc + (g*32 + lane)*32);
                const uint4 bh1 = *(const uint4*)(Wc + (g*32 + lane)*32 + 16);
                const uint4 bl0 = *(const uint4*)(Wc + 4096 + (g*32 + lane)*32);
                const uint4 bl1 = *(const uint4*)(Wc + 4096 + (g*32 + lane)*32 + 16);
                const uint32_t* ahp = (const uint32_t*)&ah;
                const uint32_t* alp = (const uint32_t*)&al;
                mma16816(acc + 0,  ahp, bh0.x, bh0.y);
                mma16816(acc + 0,  ahp, bl0.x, bl0.y);
                mma16816(acc + 0,  alp, bh0.x, bh0.y);
                mma16816(acc + 4,  ahp, bh0.z, bh0.w);
                mma16816(acc + 4,  ahp, bl0.z, bl0.w);
                mma16816(acc + 4,  alp, bh0.z, bh0.w);
                mma16816(acc + 8,  ahp, bh1.x, bh1.y);
                mma16816(acc + 8,  ahp, bl1.x, bl1.y);
                mma16816(acc + 8,  alp, bh1.x, bh1.y);
                mma16816(acc + 12, ahp, bh1.z, bh1.w);
                mma16816(acc + 12, ahp, bl1.z, bl1.w);
                mma16816(acc + 12, alp, bh1.z, bh1.w);
            }
            __syncthreads();     // stage st free before producer re-arms it
        }

        // write partials: gh=0 -> Zs, gh=1 -> Zs2
        {
            float* Zt = gh ? Zs2 : Zs;
            #pragma unroll
            for (int nt = 0; nt < 4; nt++) {
                #pragma unroll
                for (int rr = 0; rr < 2; rr++) {
                    int b = mt*16 + (lane >> 2) + rr*8;
                    int n = nt*8 + 2*(lane & 3);
                    Zt[b*33 + n]     = acc[nt*4 + rr*2];
                    Zt[b*33 + n + 1] = acc[nt*4 + rr*2 + 1];
                }
            }
        }
        __syncthreads();

        // gates: warp wid = hidden j, lanes cover b and b+32 (bias already in GEMM)
        {
            uint32_t* tb = g_hA + ((size_t)(dir*2 + ((s + 1) & 1))*10 + ch_h)*4096;
            __nv_bfloat16* hp = (__nv_bfloat16*)tb;
            float zi = Zs[bA*33 + wid]      + Zs2[bA*33 + wid];
            float zf = Zs[bA*33 + 8 + wid]  + Zs2[bA*33 + 8 + wid];
            float zg = Zs[bA*33 + 16 + wid] + Zs2[bA*33 + 16 + wid];
            float zo = Zs[bA*33 + 24 + wid] + Zs2[bA*33 + 24 + wid];
            float cn = sigm(zf)*crA + sigm(zi)*tanh_s(zg);
            crA = cn;
            float h = sigm(zo)*tanh_s(cn);
            if (s < LA) acA += h;
            __nv_bfloat16 hh = __float2bfloat16_rn(h);
            __nv_bfloat16 hl = __float2bfloat16_rn(h - __bfloat162float(hh));
            hp[offA*2 + hsel] = hh;
            hp[4096 + offA*2 + hsel] = hl;

            zi = Zs[bB*33 + wid]      + Zs2[bB*33 + wid];
            zf = Zs[bB*33 + 8 + wid]  + Zs2[bB*33 + 8 + wid];
            zg = Zs[bB*33 + 16 + wid] + Zs2[bB*33 + 16 + wid];
            zo = Zs[bB*33 + 24 + wid] + Zs2[bB*33 + 24 + wid];
            cn = sigm(zf)*crB + sigm(zi)*tanh_s(zg);
            crB = cn;
            h = sigm(zo)*tanh_s(cn);
            if (s < LB) acB += h;
            hh = __float2bfloat16_rn(h);
            hl = __float2bfloat16_rn(h - __bfloat162float(hh));
            hp[offB*2 + hsel] = hh;
            hp[4096 + offB*2 + hsel] = hl;
        }
        __threadfence();
        __syncthreads();
        if (tid == 0) atomicAdd(&bar[s], 1);   // release step s
    }

    const float inv = 1.0f / (float)SEQ;
    out[bA*1200 + dir*HID + c0 + wid] = acA * inv;
    out[bB*1200 + dir*HID + c0 + wid] = acB * inv;
}

// ---------------- launch ----------------
extern "C" void kernel_launch(void* const* d_in, const int* in_sizes, int n_in,
                              void* d_out, int out_size) {
    (void)in_sizes; (void)out_size;
    const float* x   = (const float*)d_in[0];
    const int*   len = (const int*)d_in[1];
    int base = (n_in >= 9) ? 3 : 2;           // skip scalar 'training' if present
    const float* Wf = (const float*)d_in[base + 0];
    const float* Uf = (const float*)d_in[base + 1];
    const float* bf = (const float*)d_in[base + 2];
    const float* Wb = (const float*)d_in[base + 3];
    const float* Ub = (const float*)d_in[base + 4];
    const float* bb = (const float*)d_in[base + 5];
    float* out = (float*)d_out;

    cudaFuncSetAttribute(brnn_lstm, cudaFuncAttributeMaxDynamicSharedMemorySize, SM_TOT);

    brnn_reset<<<160, 256>>>();
    brnn_xprep<<<dim3(SEQ, 2), NTHR>>>(x, len);
    brnn_lstm<<<dim3(NBLK, 2), NTHR, SM_TOT>>>(Wf, Uf, bf, Wb, Ub, bb, len, out);
}